// round 17
// baseline (speedup 1.0000x reference)
#include <cuda_runtime.h>
#include <cuda_fp16.h>
#include <math.h>

#define BATCH 2
#define SEQ   2048
#define DIM   1024
#define HEADS 16
#define HDIM  64
#define MROWS (BATCH * SEQ)     /* 4096 */
#define NQKV  (3 * DIM)         /* 3072 */
#define QKLD  (2 * DIM)         /* row stride (halves) of qk buffer */

// Scratch (device globals; fp16 → ~42MB total).
__device__ __half g_qk [(size_t)MROWS * QKLD];                   // 16.8 MB (q|k per row)
__device__ __half g_vt [(size_t)(BATCH * DIM) * SEQ];            //  8.4 MB (v transposed)
__device__ __half g_att[(size_t)MROWS * DIM];                    //  8.4 MB (xr alias, then att)
__device__ __half g_wrs[(size_t)DIM * NQKV + (size_t)DIM * DIM]; //  8.4 MB (wr_t | owr_t)

// ---------------------------------------------------------------------------
// helpers
// ---------------------------------------------------------------------------
__device__ __forceinline__ void mma_f16(float c[4], const unsigned a[4], const unsigned b[2]) {
    asm volatile(
        "mma.sync.aligned.m16n8k16.row.col.f32.f16.f16.f32 "
        "{%0,%1,%2,%3}, {%4,%5,%6,%7}, {%8,%9}, {%0,%1,%2,%3};\n"
        : "+f"(c[0]), "+f"(c[1]), "+f"(c[2]), "+f"(c[3])
        : "r"(a[0]), "r"(a[1]), "r"(a[2]), "r"(a[3]), "r"(b[0]), "r"(b[1]));
}

__device__ __forceinline__ void ldsm_x4(unsigned r[4], const __half* p) {
    unsigned a = (unsigned)__cvta_generic_to_shared(p);
    asm volatile("ldmatrix.sync.aligned.m8n8.x4.shared.b16 {%0,%1,%2,%3}, [%4];"
                 : "=r"(r[0]), "=r"(r[1]), "=r"(r[2]), "=r"(r[3]) : "r"(a));
}

__device__ __forceinline__ void cp16(__half* s, const __half* g) {
    unsigned sa = (unsigned)__cvta_generic_to_shared(s);
    asm volatile("cp.async.cg.shared.global [%0], [%1], 16;\n" :: "r"(sa), "l"(g));
}
#define CP_COMMIT() asm volatile("cp.async.commit_group;\n" ::: "memory")
#define CP_WAIT(N)  asm volatile("cp.async.wait_group %0;\n" :: "n"(N) : "memory")

// ---------------------------------------------------------------------------
// Prep kernels
// ---------------------------------------------------------------------------
__global__ __launch_bounds__(256) void round_half_kernel(
    const float* __restrict__ src, __half* __restrict__ dst, int n4)
{
    const int i = (blockIdx.x * 256 + threadIdx.x);
    if (i < n4) {
        float4 v = ((const float4*)src)[i];
        ((__half2*)dst)[2 * i]     = __floats2half2_rn(v.x, v.y);
        ((__half2*)dst)[2 * i + 1] = __floats2half2_rn(v.z, v.w);
    }
}

// dst[n][k] = half(src[k][n]);  src fp32 [K][N]. 32x32 smem tiles.
__global__ __launch_bounds__(256) void round_transpose_kernel(
    const float* __restrict__ src, __half* __restrict__ dst, int K, int N)
{
    __shared__ float t[32][33];
    const int n0 = blockIdx.x * 32;
    const int k0 = blockIdx.y * 32;
    const int tx = threadIdx.x & 31;
    const int ty = threadIdx.x >> 5;       // 0..7
#pragma unroll
    for (int i = 0; i < 32; i += 8)
        t[ty + i][tx] = src[(size_t)(k0 + ty + i) * N + n0 + tx];
    __syncthreads();
#pragma unroll
    for (int i = 0; i < 32; i += 8)
        dst[(size_t)(n0 + ty + i) * K + k0 + tx] = __float2half_rn(t[tx][ty + i]);
}

// ---------------------------------------------------------------------------
// FP16 GEMM: C[M,N] = A[M,K] @ Wt[N,K]^T + bias[N]  (unchanged from R16)
// Block 128x128x64, 8 warps, warp tile 64x32, mma m16n8k16, all LDSM.
// ---------------------------------------------------------------------------
#define BM 128
#define BN 128
#define BK 64
#define TPH 72                                 /* tile pitch (halves): 144B rows */
#define TSZH (128 * TPH)                       /* one tile (halves) */
#define GEMM_SMEM ((4 * TSZH) * (int)sizeof(__half))   /* 73728 B */

template <bool HALF_OUT, bool VT>
__global__ __launch_bounds__(256, 2) void gemm_f16_kernel(
    const __half* __restrict__ A, const __half* __restrict__ Wt,
    const float* __restrict__ bias,
    __half* __restrict__ Ch, float* __restrict__ Cf, __half* __restrict__ Cvt,
    int M, int N, int K, int ldc)
{
    extern __shared__ __half hdyn[];
    __half* As = hdyn;                // [2][128][TPH]
    __half* Bs = hdyn + 2 * TSZH;     // [2][128][TPH]  (rows = n)

    const int tid  = threadIdx.x;
    const int lane = tid & 31;
    const int warp = tid >> 5;
    const int wr   = warp >> 2;
    const int wc   = warp & 3;

    const int m0 = blockIdx.y * BM;
    const int n0 = blockIdx.x * BN;

    const int lrow = tid >> 3;
    const int lcol = (tid & 7) * 8;

    const int T = K / BK;

    auto loadtile = [&](int t) {
        __half* as = As + (t & 1) * TSZH;
        __half* bs = Bs + (t & 1) * TSZH;
        const int k0 = t * BK;
#pragma unroll
        for (int i = 0; i < 4; ++i)
            cp16(&as[(lrow + 32 * i) * TPH + lcol],
                 A + (size_t)(m0 + lrow + 32 * i) * K + k0 + lcol);
#pragma unroll
        for (int i = 0; i < 4; ++i)
            cp16(&bs[(lrow + 32 * i) * TPH + lcol],
                 Wt + (size_t)(n0 + lrow + 32 * i) * K + k0 + lcol);
        CP_COMMIT();
    };

    float acc[4][4][4];
#pragma unroll
    for (int mi = 0; mi < 4; ++mi)
#pragma unroll
        for (int nj = 0; nj < 4; ++nj)
#pragma unroll
            for (int r = 0; r < 4; ++r) acc[mi][nj][r] = 0.f;

    const int sm_row = lane & 15;
    const int sm_k8  = (lane >> 4) * 8;

    loadtile(0);

    for (int t = 0; t < T; ++t) {
        CP_WAIT(0);
        __syncthreads();
        if (t + 1 < T) loadtile(t + 1);

        const __half* as = As + (t & 1) * TSZH;
        const __half* bs = Bs + (t & 1) * TSZH;

#pragma unroll
        for (int ks = 0; ks < 4; ++ks) {
            unsigned af[4][4], bq[2][4];
            const __half* ab = as + (wr * 64 + sm_row) * TPH + ks * 16 + sm_k8;
            const __half* bb = bs + (wc * 32 + sm_row) * TPH + ks * 16 + sm_k8;
#pragma unroll
            for (int mi = 0; mi < 4; ++mi)
                ldsm_x4(af[mi], ab + mi * 16 * TPH);
#pragma unroll
            for (int p = 0; p < 2; ++p)
                ldsm_x4(bq[p], bb + p * 16 * TPH);
#pragma unroll
            for (int mi = 0; mi < 4; ++mi)
#pragma unroll
                for (int p = 0; p < 2; ++p) {
                    unsigned b0[2] = {bq[p][0], bq[p][2]};
                    unsigned b1[2] = {bq[p][1], bq[p][3]};
                    mma_f16(acc[mi][2 * p],     af[mi], b0);
                    mma_f16(acc[mi][2 * p + 1], af[mi], b1);
                }
        }
    }

    const int grp = lane >> 2;
    const int qid = lane & 3;
    const bool vmode = VT && (n0 >= 2 * DIM);
#pragma unroll
    for (int mi = 0; mi < 4; ++mi) {
#pragma unroll
        for (int nj = 0; nj < 4; ++nj) {
            const int row = m0 + wr * 64 + mi * 16 + grp;
            const int col = n0 + wc * 32 + nj * 8 + 2 * qid;
            const float b0 = bias[col];
            const float b1 = bias[col + 1];
            const float c00 = acc[mi][nj][0] + b0, c01 = acc[mi][nj][1] + b1;
            const float c10 = acc[mi][nj][2] + b0, c11 = acc[mi][nj][3] + b1;
            if (HALF_OUT) {
                if (vmode) {
                    const int bb = row >> 11;
                    const int ss = row & (SEQ - 1);
                    const int cc = col - 2 * DIM;
                    __half* base = Cvt + ((size_t)(bb * DIM + cc)) * SEQ + ss;
                    base[0]       = __float2half_rn(c00);
                    base[SEQ]     = __float2half_rn(c01);
                    base[8]       = __float2half_rn(c10);
                    base[SEQ + 8] = __float2half_rn(c11);
                } else {
                    *(__half2*)&Ch[(size_t)row * ldc + col] = __floats2half2_rn(c00, c01);
                    *(__half2*)&Ch[(size_t)(row + 8) * ldc + col] = __floats2half2_rn(c10, c11);
                }
            } else {
                *(float2*)&Cf[(size_t)row * ldc + col] = make_float2(c00, c01);
                *(float2*)&Cf[(size_t)(row + 8) * ldc + col] = make_float2(c10, c11);
            }
        }
    }
}

// ---------------------------------------------------------------------------
// Flash attention (causal), fp16 MMA. Q-tile 128 (8 warps, 256 thr),
// double-buffered cp.async KV. smem 73.7KB -> 2 CTAs/SM (16 warps).
// Grid: (SEQ/128, B*H).
// ---------------------------------------------------------------------------
#define KVT (64 * TPH)                         /* one K or V stage (halves) */
#define FLASH_SMEM ((2 * 128 * TPH + 4 * KVT) * (int)sizeof(__half))  /* 73728 B */

__global__ __launch_bounds__(256, 2) void flash_f16_kernel(
    const __half* __restrict__ qk, const __half* __restrict__ vt,
    __half* __restrict__ att)
{
    extern __shared__ __half hsm[];
    __half* Qs = hsm;                  // 128*TPH
    __half* Ps = Qs + 128 * TPH;       // 128*TPH (warp-private 16-row slices)
    __half* KV = Ps + 128 * TPH;       // [2 stages][K 64*TPH | V 64*TPH]

    const int tid  = threadIdx.x;
    const int lane = tid & 31;
    const int warp = tid >> 5;     // 0..7, 16 queries each
    const int grp  = lane >> 2;
    const int qid  = lane & 3;

    const int bh = blockIdx.y;
    const int b  = bh / HEADS;
    const int h  = bh % HEADS;
    const int qt = gridDim.x - 1 - blockIdx.x;   // heavy tiles first
    const int q0 = qt * 128;
    const float scale = 0.125f;

    const __half* qbase = qk + (size_t)(b * SEQ) * QKLD + h * HDIM;
    const __half* kbase = qbase + DIM;
    const __half* vbase = vt + ((size_t)(b * DIM + h * HDIM)) * SEQ;

    // KV loader lanes: 64 rows x 64 halves per matrix, 2 cp16 each per matrix
    const int kr = tid >> 2;            // 0..63
    const int kc = (tid & 3) * 16;      // 0,16,32,48 halves

    auto loadKV = [&](int t) {
        __half* ks = KV + (t & 1) * 2 * KVT;
        __half* vs = ks + KVT;
        const int k0 = t * 64;
        // K tile: [kv][d]
        cp16(&ks[kr * TPH + kc],     kbase + (size_t)(k0 + kr) * QKLD + kc);
        cp16(&ks[kr * TPH + kc + 8], kbase + (size_t)(k0 + kr) * QKLD + kc + 8);
        // V tile: [d][kv]
        cp16(&vs[kr * TPH + kc],     vbase + (size_t)kr * SEQ + k0 + kc);
        cp16(&vs[kr * TPH + kc + 8], vbase + (size_t)kr * SEQ + k0 + kc + 8);
        CP_COMMIT();
    };

    loadKV(0);

    // Load Q tile (128 rows x 64 halves)
    {
        const int lr = tid >> 3;        // 0..31
        const int lc = (tid & 7) * 8;   // 0..56
#pragma unroll
        for (int i = 0; i < 4; ++i) {
            const int row = lr + 32 * i;
            *(uint4*)&Qs[row * TPH + lc] =
                *(const uint4*)(qbase + (size_t)(q0 + row) * QKLD + lc);
        }
    }
    __syncthreads();

    // Q fragments register-resident
    const int sm_row = lane & 15;
    const int sm_k8  = (lane >> 4) * 8;
    unsigned qf[4][4];
#pragma unroll
    for (int ks = 0; ks < 4; ++ks)
        ldsm_x4(qf[ks], &Qs[(warp * 16 + sm_row) * TPH + ks * 16 + sm_k8]);

    float m0r = -INFINITY, m1r = -INFINITY, l0 = 0.f, l1 = 0.f;
    float o[8][4];
#pragma unroll
    for (int j = 0; j < 8; ++j)
#pragma unroll
        for (int r = 0; r < 4; ++r) o[j][r] = 0.f;

    const int ntiles = 2 * qt + 2;
    for (int t = 0; t < ntiles; ++t) {
        const int k0 = t * 64;
        CP_WAIT(0);              // KV tile t resident
        __syncthreads();         // all warps done with stage t^1
        if (t + 1 < ntiles) loadKV(t + 1);

        const __half* Ks  = KV + (t & 1) * 2 * KVT;
        const __half* Vts = Ks + KVT;

        // S = Q K^T  (warp tile 16x64)
        float s[8][4];
#pragma unroll
        for (int j = 0; j < 8; ++j)
            s[j][0] = s[j][1] = s[j][2] = s[j][3] = 0.f;
#pragma unroll
        for (int ks = 0; ks < 4; ++ks) {
#pragma unroll
            for (int jj = 0; jj < 4; ++jj) {
                unsigned kq[4];
                ldsm_x4(kq, &Ks[(jj * 16 + sm_row) * TPH + ks * 16 + sm_k8]);
                unsigned b0[2] = {kq[0], kq[2]};
                unsigned b1[2] = {kq[1], kq[3]};
                mma_f16(s[2 * jj],     qf[ks], b0);
                mma_f16(s[2 * jj + 1], qf[ks], b1);
            }
        }

        // scale + causal mask (last two tiles overlap the diagonal band)
        const bool diag = (t >= ntiles - 2);
        const int qi0 = q0 + warp * 16 + grp;
#pragma unroll
        for (int j = 0; j < 8; ++j) {
#pragma unroll
            for (int r = 0; r < 4; ++r) {
                float v = s[j][r] * scale;
                if (diag) {
                    const int kj = k0 + j * 8 + 2 * qid + (r & 1);
                    const int qi = qi0 + ((r >= 2) ? 8 : 0);
                    if (kj > qi) v = -INFINITY;
                }
                s[j][r] = v;
            }
        }

        // online softmax (rows grp and grp+8)
        float mx0 = -INFINITY, mx1 = -INFINITY;
#pragma unroll
        for (int j = 0; j < 8; ++j) {
            mx0 = fmaxf(mx0, fmaxf(s[j][0], s[j][1]));
            mx1 = fmaxf(mx1, fmaxf(s[j][2], s[j][3]));
        }
        mx0 = fmaxf(mx0, __shfl_xor_sync(0xffffffffu, mx0, 1));
        mx0 = fmaxf(mx0, __shfl_xor_sync(0xffffffffu, mx0, 2));
        mx1 = fmaxf(mx1, __shfl_xor_sync(0xffffffffu, mx1, 1));
        mx1 = fmaxf(mx1, __shfl_xor_sync(0xffffffffu, mx1, 2));

        const float nm0 = fmaxf(m0r, mx0);
        const float nm1 = fmaxf(m1r, mx1);
        const float corr0 = __expf(m0r - nm0);
        const float corr1 = __expf(m1r - nm1);
        m0r = nm0; m1r = nm1;

        float sum0 = 0.f, sum1 = 0.f;
#pragma unroll
        for (int j = 0; j < 8; ++j) {
            s[j][0] = __expf(s[j][0] - nm0);
            s[j][1] = __expf(s[j][1] - nm0);
            s[j][2] = __expf(s[j][2] - nm1);
            s[j][3] = __expf(s[j][3] - nm1);
            sum0 += s[j][0] + s[j][1];
            sum1 += s[j][2] + s[j][3];
        }
        sum0 += __shfl_xor_sync(0xffffffffu, sum0, 1);
        sum0 += __shfl_xor_sync(0xffffffffu, sum0, 2);
        sum1 += __shfl_xor_sync(0xffffffffu, sum1, 1);
        sum1 += __shfl_xor_sync(0xffffffffu, sum1, 2);
        l0 = l0 * corr0 + sum0;
        l1 = l1 * corr1 + sum1;
#pragma unroll
        for (int j = 0; j < 8; ++j) {
            o[j][0] *= corr0; o[j][1] *= corr0;
            o[j][2] *= corr1; o[j][3] *= corr1;
        }

        // P fragments -> smem fp16 (warp-private 16-row slice)
#pragma unroll
        for (int j = 0; j < 8; ++j) {
            *(__half2*)&Ps[(warp * 16 + grp) * TPH + j * 8 + 2 * qid] =
                __floats2half2_rn(s[j][0], s[j][1]);
            *(__half2*)&Ps[(warp * 16 + grp + 8) * TPH + j * 8 + 2 * qid] =
                __floats2half2_rn(s[j][2], s[j][3]);
        }
        __syncwarp();

        // O += P @ V
#pragma unroll
        for (int ks = 0; ks < 4; ++ks) {
            unsigned pf[4];
            ldsm_x4(pf, &Ps[(warp * 16 + sm_row) * TPH + ks * 16 + sm_k8]);
#pragma unroll
            for (int dd = 0; dd < 4; ++dd) {
                unsigned vq[4];
                ldsm_x4(vq, &Vts[(dd * 16 + sm_row) * TPH + ks * 16 + sm_k8]);
                unsigned b0[2] = {vq[0], vq[2]};
                unsigned b1[2] = {vq[1], vq[3]};
                mma_f16(o[2 * dd],     pf, b0);
                mma_f16(o[2 * dd + 1], pf, b1);
            }
        }
    }

    // write normalized output (fp16: feeds out-proj MMA directly)
    const float inv0 = 1.0f / l0;
    const float inv1 = 1.0f / l1;
    const int row0 = q0 + warp * 16 + grp;
#pragma unroll
    for (int j = 0; j < 8; ++j) {
        const int col = h * HDIM + j * 8 + 2 * qid;
        *(__half2*)&att[((size_t)(b * SEQ) + row0) * DIM + col] =
            __floats2half2_rn(o[j][0] * inv0, o[j][1] * inv0);
        *(__half2*)&att[((size_t)(b * SEQ) + row0 + 8) * DIM + col] =
            __floats2half2_rn(o[j][2] * inv1, o[j][3] * inv1);
    }
}

// ---------------------------------------------------------------------------
extern "C" void kernel_launch(void* const* d_in, const int* in_sizes, int n_in,
                              void* d_out, int out_size)
{
    const float* x      = (const float*)d_in[0];   // [B,S,D]
    const float* qkv_w  = (const float*)d_in[1];   // [D, 3D]
    const float* qkv_b  = (const float*)d_in[2];   // [3D]
    const float* out_w  = (const float*)d_in[3];   // [D, D]
    const float* out_b  = (const float*)d_in[4];   // [D]
    float* out = (float*)d_out;

    __half *qk_buf, *vt_buf, *att_buf, *wrs;
    cudaGetSymbolAddress((void**)&qk_buf, g_qk);
    cudaGetSymbolAddress((void**)&vt_buf, g_vt);
    cudaGetSymbolAddress((void**)&att_buf, g_att);
    cudaGetSymbolAddress((void**)&wrs, g_wrs);

    __half* xr    = att_buf;                              // alias (dead before flash)
    __half* wr_t  = wrs;                                  // [NQKV][DIM]
    __half* owr_t = wrs + (size_t)DIM * NQKV;             // [DIM][DIM]

    cudaFuncSetAttribute(gemm_f16_kernel<true, true>,
                         cudaFuncAttributeMaxDynamicSharedMemorySize, GEMM_SMEM);
    cudaFuncSetAttribute(gemm_f16_kernel<false, false>,
                         cudaFuncAttributeMaxDynamicSharedMemorySize, GEMM_SMEM);
    cudaFuncSetAttribute(flash_f16_kernel,
                         cudaFuncAttributeMaxDynamicSharedMemorySize, FLASH_SMEM);

    // 0) prep
    {
        int n4 = MROWS * DIM / 4;
        round_half_kernel<<<(n4 + 255) / 256, 256>>>(x, xr, n4);
        dim3 g1(NQKV / 32, DIM / 32);
        round_transpose_kernel<<<g1, 256>>>(qkv_w, wr_t, DIM, NQKV);
        dim3 g2(DIM / 32, DIM / 32);
        round_transpose_kernel<<<g2, 256>>>(out_w, owr_t, DIM, DIM);
    }
    // 1) QKV projection
    {
        dim3 grid(NQKV / BN, MROWS / BM);
        gemm_f16_kernel<true, true><<<grid, 256, GEMM_SMEM>>>(
            xr, wr_t, qkv_b, qk_buf, nullptr, vt_buf, MROWS, NQKV, DIM, QKLD);
    }
    // 2) Causal flash attention (Q-tile 128, pipelined KV)
    {
        dim3 grid(SEQ / 128, BATCH * HEADS);
        flash_f16_kernel<<<grid, 256, FLASH_SMEM>>>(qk_buf, vt_buf, att_buf);
    }
    // 3) Output projection (fp32 out)
    {
        dim3 grid(DIM / BN, MROWS / BM);
        gemm_f16_kernel<false, false><<<grid, 256, GEMM_SMEM>>>(
            att_buf, owr_t, out_b, nullptr, out, nullptr, MROWS, DIM, DIM, DIM);
    }
}